// round 11
// baseline (speedup 1.0000x reference)
#include <cuda_runtime.h>
#include <cuda_bf16.h>
#include <cstdint>

// ---------------------------------------------------------------------------
// Dual-branch GCN + MLP, single launch, 3 CTAs/SM.
// L1 GEMM: A fragments LDG'd directly from global X (barrier-free); B = W^T
// staged once as bank-exact bf16 hi/lo planes. Split-bf16: D = AhBh+AhBl+AlBh.
// agg1 emits bf16 hi/lo planes consumed by layer-2 MMA; agg2 fused w/ pooling.
// Edge cols packed to u8 LOCAL indices in smem; edge vals read as warp-uniform
// __ldg float4 (L2 broadcast). In-kernel MLP via per-graph atomic ticket.
// rows = repeat(arange(N),16) -> node r owns edges [16r,16r+16); cols in-graph.
// ---------------------------------------------------------------------------

#define BGRAPHS 1024
#define DEG 16

// smem layout (bytes)
#define W1T_B   0        // W1^T hi [32][232] bf16 (464B rows) = 14848
#define W1T_LO  14848    // W1^T lo — dies after L1 GEMM
#define HB_HI_B 0        // hb hi [<=256][36] bf16 (aliases W1T)
#define HB_LO_B 14848
#define WBT_B   29696    // Wb^T hi [32][40] bf16 = 2560
#define WBT_LO  32256
#define SUP_B   34816    // sup [200][34] f32 = 27200
#define COLS_B  62016    // u8 local cols [200*16] = 3200
#define RED_B   29696    // pool scratch, aliases WBT (dead by then)
#define SMEM_BYTES 65280

__device__ float g_feat[BGRAPHS * 128];
__device__ int   g_cnt[BGRAPHS];          // zero-init; re-armed after each use

__device__ __forceinline__ void hmma(float* c, uint32_t a0, uint32_t a1,
                                     uint32_t a2, uint32_t a3,
                                     uint32_t b0, uint32_t b1) {
    asm("mma.sync.aligned.m16n8k16.row.col.f32.bf16.bf16.f32 "
        "{%0,%1,%2,%3}, {%4,%5,%6,%7}, {%8,%9}, {%0,%1,%2,%3};"
        : "+f"(c[0]), "+f"(c[1]), "+f"(c[2]), "+f"(c[3])
        : "r"(a0), "r"(a1), "r"(a2), "r"(a3), "r"(b0), "r"(b1));
}
__device__ __forceinline__ void split2(float2 v, uint32_t& h, uint32_t& l) {
    __nv_bfloat162 h2 = __float22bfloat162_rn(v);
    float2 hf = __bfloat1622float2(h2);
    __nv_bfloat162 l2 = __float22bfloat162_rn(make_float2(v.x - hf.x, v.y - hf.y));
    h = *(uint32_t*)&h2;
    l = *(uint32_t*)&l2;
}

// MLP head for one sample (one warp).
__device__ __forceinline__ void mlp_tail(
    int g, int lane,
    const float* __restrict__ fc1W, const float* __restrict__ fc1b,
    const float* __restrict__ fc2W, const float* __restrict__ fc2b,
    const float* __restrict__ fc3W, const float* __restrict__ fc3b,
    float* __restrict__ out)
{
    const float* f = g_feat + g * 128;
    float fr0 = f[lane];
    float fr1 = f[32 + lane];
    float fr2 = f[64 + lane];
    float fr3 = f[96 + lane];

    float a0 = __ldg(fc1b + lane), a1 = 0.f, a2 = 0.f, a3 = 0.f;
    #pragma unroll
    for (int j = 0; j < 32; j++) {
        float f0 = __shfl_sync(0xffffffffu, fr0, j);
        float f1 = __shfl_sync(0xffffffffu, fr1, j);
        float f2 = __shfl_sync(0xffffffffu, fr2, j);
        float f3 = __shfl_sync(0xffffffffu, fr3, j);
        a0 = fmaf(f0, __ldg(fc1W + j * 32 + lane), a0);
        a1 = fmaf(f1, __ldg(fc1W + (32 + j) * 32 + lane), a1);
        a2 = fmaf(f2, __ldg(fc1W + (64 + j) * 32 + lane), a2);
        a3 = fmaf(f3, __ldg(fc1W + (96 + j) * 32 + lane), a3);
    }
    float h1 = fmaxf((a0 + a1) + (a2 + a3), 0.f);

    const int l16 = lane & 15;
    float b0 = __ldg(fc2b + l16), b1 = 0.f;
    #pragma unroll
    for (int k = 0; k < 32; k += 2) {
        float ha = __shfl_sync(0xffffffffu, h1, k);
        float hb = __shfl_sync(0xffffffffu, h1, k + 1);
        b0 = fmaf(ha, __ldg(fc2W + k * 16 + l16), b0);
        b1 = fmaf(hb, __ldg(fc2W + (k + 1) * 16 + l16), b1);
    }
    float h2 = fmaxf(b0 + b1, 0.f);

    const int l2 = lane & 1;
    float o = __ldg(fc3b + l2);
    #pragma unroll
    for (int k = 0; k < 16; k++) {
        float hk = __shfl_sync(0xffffffffu, h2, k);
        o = fmaf(hk, __ldg(fc3W + k * 2 + l2), o);
    }
    if (lane < 2) out[g * 2 + l2] = o;
}

template<int NP, int KC, int NTILES>
__device__ __forceinline__ void run_branch(
    char* smb, int g,
    const float* __restrict__ X, const int* __restrict__ cols,
    const float* __restrict__ vals,
    const float* __restrict__ Wa, const float* __restrict__ ba,
    const float* __restrict__ Wb, const float* __restrict__ bb, int foff,
    const float* __restrict__ fc1W, const float* __restrict__ fc1b,
    const float* __restrict__ fc2W, const float* __restrict__ fc2b,
    const float* __restrict__ fc3W, const float* __restrict__ fc3b,
    float* __restrict__ out)
{
    float* sup = (float*)(smb + SUP_B);

    const int tid  = threadIdx.x;
    const int lane = tid & 31;
    const int wid  = tid >> 5;
    const int gq   = lane >> 2;
    const int tq   = lane & 3;
    const int gbase = g * NP;
    const float* Xg = X + (size_t)gbase * NP;

    // ---- stage edge cols as u8 LOCAL indices (NP <= 200 < 256) ----
    {
        const int4* gc = (const int4*)(cols + (size_t)gbase * DEG);
        for (int i = tid; i < NP * 4; i += 256) {
            int4 c = __ldg(gc + i);
            uint32_t p = (uint32_t)(c.x - gbase)
                       | ((uint32_t)(c.y - gbase) << 8)
                       | ((uint32_t)(c.z - gbase) << 16)
                       | ((uint32_t)(c.w - gbase) << 24);
            *(uint32_t*)(smb + COLS_B + i * 4) = p;
        }
    }
    // ---- stage W1^T hi/lo planes once ([32][232] bf16 rows, bank-exact) ----
    for (int i = tid; i < 32 * KC * 16; i += 256) {
        int kp = i >> 5, n = i & 31;
        int k = 2 * kp;
        float2 v = make_float2(0.f, 0.f);
        if (k < NP)     v.x = Wa[k * 32 + n];
        if (k + 1 < NP) v.y = Wa[(k + 1) * 32 + n];
        uint32_t h, l;
        split2(v, h, l);
        *(uint32_t*)(smb + W1T_B  + n * 464 + kp * 4) = h;
        *(uint32_t*)(smb + W1T_LO + n * 464 + kp * 4) = l;
    }
    // ---- stage Wb^T hi/lo planes once ([32][40] bf16) ----
    for (int i = tid; i < 32 * 20; i += 256) {
        int kp = i >> 5, n = i & 31;
        int k = 2 * kp;
        float2 v = make_float2(0.f, 0.f);
        if (k < 32) { v.x = Wb[k * 32 + n]; v.y = Wb[(k + 1) * 32 + n]; }
        uint32_t h, l;
        split2(v, h, l);
        *(uint32_t*)(smb + WBT_B  + n * 80 + kp * 4) = h;
        *(uint32_t*)(smb + WBT_LO + n * 80 + kp * 4) = l;
    }
    __syncthreads();

    float acc[4][4];
    auto zero_acc = [&]() {
        #pragma unroll
        for (int i = 0; i < 4; i++)
            #pragma unroll
            for (int j = 0; j < 4; j++) acc[i][j] = 0.f;
    };
    auto epilogue = [&](int r0) {
        int row0 = r0 + wid * 16 + gq;
        #pragma unroll
        for (int nt = 0; nt < 4; nt++) {
            if (row0 < NP)
                *(float2*)(sup + row0 * 34 + nt * 8 + 2 * tq) =
                    make_float2(acc[nt][0], acc[nt][1]);
            if (row0 + 8 < NP)
                *(float2*)(sup + (row0 + 8) * 34 + nt * 8 + 2 * tq) =
                    make_float2(acc[nt][2], acc[nt][3]);
        }
    };

    // ================= Layer 1: sup = X_g @ Wa (barrier-free) =============
    for (int t = 0; t < NTILES; t++) {
        const int r0 = t * 128;
        const int row0 = r0 + wid * 16 + gq;
        const int row1 = row0 + 8;
        const float* p0 = Xg + (size_t)row0 * NP;
        const float* p1 = Xg + (size_t)row1 * NP;

        float2 xa[8];
        auto pfA = [&](int kc) {
            #pragma unroll
            for (int s = 0; s < 2; s++) {
                int ka = kc * 32 + s * 16 + 2 * tq;
                int kb = ka + 8;
                xa[s*4+0] = (row0 < NP && ka < NP) ? *(const float2*)(p0 + ka) : make_float2(0.f,0.f);
                xa[s*4+1] = (row1 < NP && ka < NP) ? *(const float2*)(p1 + ka) : make_float2(0.f,0.f);
                xa[s*4+2] = (row0 < NP && kb < NP) ? *(const float2*)(p0 + kb) : make_float2(0.f,0.f);
                xa[s*4+3] = (row1 < NP && kb < NP) ? *(const float2*)(p1 + kb) : make_float2(0.f,0.f);
            }
        };

        pfA(0);
        zero_acc();
        #pragma unroll
        for (int kc = 0; kc < KC; kc++) {
            uint32_t ah[8], al[8];
            #pragma unroll
            for (int j = 0; j < 8; j++) split2(xa[j], ah[j], al[j]);
            if (kc + 1 < KC) pfA(kc + 1);          // overlap LDG with MMA
            #pragma unroll
            for (int s = 0; s < 2; s++) {
                uint32_t bh[4][2], bl[4][2];
                #pragma unroll
                for (int nt = 0; nt < 4; nt++) {
                    const char* p = smb + W1T_B + (nt*8+gq) * 464
                                  + (kc*32 + s*16 + 2*tq) * 2;
                    bh[nt][0] = *(const uint32_t*)p;
                    bh[nt][1] = *(const uint32_t*)(p + 16);
                    bl[nt][0] = *(const uint32_t*)(p + W1T_LO);
                    bl[nt][1] = *(const uint32_t*)(p + W1T_LO + 16);
                }
                #pragma unroll
                for (int nt = 0; nt < 4; nt++) {
                    hmma(acc[nt], ah[4*s],ah[4*s+1],ah[4*s+2],ah[4*s+3],
                         bh[nt][0], bh[nt][1]);
                    hmma(acc[nt], ah[4*s],ah[4*s+1],ah[4*s+2],ah[4*s+3],
                         bl[nt][0], bl[nt][1]);
                    hmma(acc[nt], al[4*s],al[4*s+1],al[4*s+2],al[4*s+3],
                         bh[nt][0], bh[nt][1]);
                }
            }
        }
        epilogue(r0);
    }
    __syncthreads();     // sup done; W1T reads done (hb planes may overwrite)

    // ===== agg1: h = relu(A @ sup + b) -> bf16 hi/lo planes =====
    {
        const float bias = __ldg(ba + lane);
        const float* supl = sup + lane;
        for (int r = wid; r < NP; r += 8) {
            uint4 cw = *(const uint4*)(smb + COLS_B + r * 16);
            const float4* v4 = (const float4*)(vals + (size_t)(gbase + r) * 16);
            float4 v0 = __ldg(v4 + 0), v1 = __ldg(v4 + 1);
            float4 v2 = __ldg(v4 + 2), v3 = __ldg(v4 + 3);
            float a0 = 0.f, a1 = 0.f;
            a0 = fmaf(v0.x, supl[( cw.x        & 255) * 34], a0);
            a1 = fmaf(v0.y, supl[((cw.x >>  8) & 255) * 34], a1);
            a0 = fmaf(v0.z, supl[((cw.x >> 16) & 255) * 34], a0);
            a1 = fmaf(v0.w, supl[( cw.x >> 24       ) * 34], a1);
            a0 = fmaf(v1.x, supl[( cw.y        & 255) * 34], a0);
            a1 = fmaf(v1.y, supl[((cw.y >>  8) & 255) * 34], a1);
            a0 = fmaf(v1.z, supl[((cw.y >> 16) & 255) * 34], a0);
            a1 = fmaf(v1.w, supl[( cw.y >> 24       ) * 34], a1);
            a0 = fmaf(v2.x, supl[( cw.z        & 255) * 34], a0);
            a1 = fmaf(v2.y, supl[((cw.z >>  8) & 255) * 34], a1);
            a0 = fmaf(v2.z, supl[((cw.z >> 16) & 255) * 34], a0);
            a1 = fmaf(v2.w, supl[( cw.z >> 24       ) * 34], a1);
            a0 = fmaf(v3.x, supl[( cw.w        & 255) * 34], a0);
            a1 = fmaf(v3.y, supl[((cw.w >>  8) & 255) * 34], a1);
            a0 = fmaf(v3.z, supl[((cw.w >> 16) & 255) * 34], a0);
            a1 = fmaf(v3.w, supl[( cw.w >> 24       ) * 34], a1);
            float h = fmaxf(a0 + a1 + bias, 0.f);
            __nv_bfloat16 hi = __float2bfloat16(h);
            __nv_bfloat16 lo = __float2bfloat16(h - __bfloat162float(hi));
            *(__nv_bfloat16*)(smb + HB_HI_B + r * 72 + lane * 2) = hi;
            *(__nv_bfloat16*)(smb + HB_LO_B + r * 72 + lane * 2) = lo;
        }
    }
    __syncthreads();

    // ===== Layer 2: sup = hb @ Wb — A from hb planes, B from Wbt planes ====
    for (int t = 0; t < NTILES; t++) {
        const int rowbase = t * 128;
        zero_acc();
        const char* Ar0h = smb + HB_HI_B + (rowbase + wid*16 + gq) * 72 + tq * 4;
        const char* Ar0l = smb + HB_LO_B + (rowbase + wid*16 + gq) * 72 + tq * 4;
        #pragma unroll
        for (int s = 0; s < 2; s++) {
            const int so = s * 32;
            uint32_t ah0 = *(const uint32_t*)(Ar0h + so);
            uint32_t ah1 = *(const uint32_t*)(Ar0h + so + 576);
            uint32_t ah2 = *(const uint32_t*)(Ar0h + so + 16);
            uint32_t ah3 = *(const uint32_t*)(Ar0h + so + 576 + 16);
            uint32_t al0 = *(const uint32_t*)(Ar0l + so);
            uint32_t al1 = *(const uint32_t*)(Ar0l + so + 576);
            uint32_t al2 = *(const uint32_t*)(Ar0l + so + 16);
            uint32_t al3 = *(const uint32_t*)(Ar0l + so + 576 + 16);
            #pragma unroll
            for (int nt = 0; nt < 4; nt++) {
                const char* Bn = smb + WBT_B  + (nt*8+gq) * 80 + tq * 4 + so;
                const char* Bl = smb + WBT_LO + (nt*8+gq) * 80 + tq * 4 + so;
                uint32_t bh0 = *(const uint32_t*)(Bn);
                uint32_t bh1 = *(const uint32_t*)(Bn + 16);
                uint32_t bl0 = *(const uint32_t*)(Bl);
                uint32_t bl1 = *(const uint32_t*)(Bl + 16);
                hmma(acc[nt], ah0, ah1, ah2, ah3, bh0, bh1);
                hmma(acc[nt], ah0, ah1, ah2, ah3, bl0, bl1);
                hmma(acc[nt], al0, al1, al2, al3, bh0, bh1);
            }
        }
        epilogue(rowbase);
    }
    __syncthreads();

    // ===== agg2 + pooling fused =====
    {
        const float bias = __ldg(bb + lane);
        const float* supl = sup + lane;
        float s = 0.f, m = -3.4e38f;
        for (int r = wid; r < NP; r += 8) {
            uint4 cw = *(const uint4*)(smb + COLS_B + r * 16);
            const float4* v4 = (const float4*)(vals + (size_t)(gbase + r) * 16);
            float4 v0 = __ldg(v4 + 0), v1 = __ldg(v4 + 1);
            float4 v2 = __ldg(v4 + 2), v3 = __ldg(v4 + 3);
            float a0 = 0.f, a1 = 0.f;
            a0 = fmaf(v0.x, supl[( cw.x        & 255) * 34], a0);
            a1 = fmaf(v0.y, supl[((cw.x >>  8) & 255) * 34], a1);
            a0 = fmaf(v0.z, supl[((cw.x >> 16) & 255) * 34], a0);
            a1 = fmaf(v0.w, supl[( cw.x >> 24       ) * 34], a1);
            a0 = fmaf(v1.x, supl[( cw.y        & 255) * 34], a0);
            a1 = fmaf(v1.y, supl[((cw.y >>  8) & 255) * 34], a1);
            a0 = fmaf(v1.z, supl[((cw.y >> 16) & 255) * 34], a0);
            a1 = fmaf(v1.w, supl[( cw.y >> 24       ) * 34], a1);
            a0 = fmaf(v2.x, supl[( cw.z        & 255) * 34], a0);
            a1 = fmaf(v2.y, supl[((cw.z >>  8) & 255) * 34], a1);
            a0 = fmaf(v2.z, supl[((cw.z >> 16) & 255) * 34], a0);
            a1 = fmaf(v2.w, supl[( cw.z >> 24       ) * 34], a1);
            a0 = fmaf(v3.x, supl[( cw.w        & 255) * 34], a0);
            a1 = fmaf(v3.y, supl[((cw.w >>  8) & 255) * 34], a1);
            a0 = fmaf(v3.z, supl[((cw.w >> 16) & 255) * 34], a0);
            a1 = fmaf(v3.w, supl[( cw.w >> 24       ) * 34], a1);
            float h = fmaxf(a0 + a1 + bias, 0.f);
            s += h;
            m = fmaxf(m, h);
        }
        float* redS = (float*)(smb + RED_B);   // aliases WBT (dead now)
        float* redM = redS + 256;
        redS[wid * 32 + lane] = s;
        redM[wid * 32 + lane] = m;
        __syncthreads();
        if (wid == 0) {
            float ss = 0.f, mm = -3.4e38f;
            #pragma unroll
            for (int i = 0; i < 8; i++) {
                ss += redS[i * 32 + lane];
                mm = fmaxf(mm, redM[i * 32 + lane]);
            }
            g_feat[g * 128 + foff + lane]      = ss / (float)NP;
            g_feat[g * 128 + foff + 32 + lane] = mm;

            // ---- MLP ticket: second CTA to finish this graph computes it ----
            __threadfence();
            __syncwarp();
            int old = 0;
            if (lane == 0) old = atomicAdd(&g_cnt[g], 1);
            old = __shfl_sync(0xffffffffu, old, 0);
            if (old == 1) {
                __threadfence();
                mlp_tail(g, lane, fc1W, fc1b, fc2W, fc2b, fc3W, fc3b, out);
                if (lane == 0) g_cnt[g] = 0;   // re-arm for graph replay
            }
        }
    }
}

__global__ void __launch_bounds__(256, 3)
branch_kernel(const float* __restrict__ x1, const int* __restrict__ cols1,
              const float* __restrict__ vals1,
              const float* __restrict__ W1a, const float* __restrict__ b1a,
              const float* __restrict__ W1b, const float* __restrict__ b1b,
              const float* __restrict__ x2, const int* __restrict__ cols2,
              const float* __restrict__ vals2,
              const float* __restrict__ W2a, const float* __restrict__ b2a,
              const float* __restrict__ W2b, const float* __restrict__ b2b,
              const float* __restrict__ fc1W, const float* __restrict__ fc1b,
              const float* __restrict__ fc2W, const float* __restrict__ fc2b,
              const float* __restrict__ fc3W, const float* __restrict__ fc3b,
              float* __restrict__ out)
{
    extern __shared__ char smb[];
    const int bid = blockIdx.x;
    if (bid < BGRAPHS) {
        run_branch<200, 7, 2>(smb, bid, x2, cols2, vals2, W2a, b2a, W2b, b2b, 64,
                              fc1W, fc1b, fc2W, fc2b, fc3W, fc3b, out);
    } else {
        run_branch<116, 4, 1>(smb, bid - BGRAPHS, x1, cols1, vals1,
                              W1a, b1a, W1b, b1b, 0,
                              fc1W, fc1b, fc2W, fc2b, fc3W, fc3b, out);
    }
}

extern "C" void kernel_launch(void* const* d_in, const int* in_sizes, int n_in,
                              void* d_out, int out_size)
{
    (void)in_sizes; (void)n_in; (void)out_size;
    const int*   cols1 = (const int*)  d_in[1];
    const float* vals1 = (const float*)d_in[2];
    const float* x1    = (const float*)d_in[3];
    const int*   cols2 = (const int*)  d_in[5];
    const float* vals2 = (const float*)d_in[6];
    const float* x2    = (const float*)d_in[7];
    const float* W1a  = (const float*)d_in[8];
    const float* b1a  = (const float*)d_in[9];
    const float* W1b  = (const float*)d_in[10];
    const float* b1b  = (const float*)d_in[11];
    const float* W2a  = (const float*)d_in[12];
    const float* b2a  = (const float*)d_in[13];
    const float* W2b  = (const float*)d_in[14];
    const float* b2b  = (const float*)d_in[15];
    const float* fc1W = (const float*)d_in[16];
    const float* fc1b = (const float*)d_in[17];
    const float* fc2W = (const float*)d_in[18];
    const float* fc2b = (const float*)d_in[19];
    const float* fc3W = (const float*)d_in[20];
    const float* fc3b = (const float*)d_in[21];
    float* out = (float*)d_out;

    cudaFuncSetAttribute(branch_kernel,
                         cudaFuncAttributeMaxDynamicSharedMemorySize, SMEM_BYTES);

    branch_kernel<<<2 * BGRAPHS, 256, SMEM_BYTES>>>(
        x1, cols1, vals1, W1a, b1a, W1b, b1b,
        x2, cols2, vals2, W2a, b2a, W2b, b2b,
        fc1W, fc1b, fc2W, fc2b, fc3W, fc3b, out);
}

// round 12
// speedup vs baseline: 1.0542x; 1.0542x over previous
#include <cuda_runtime.h>
#include <cuda_bf16.h>
#include <cstdint>

// ---------------------------------------------------------------------------
// Dual-branch GCN + MLP, single launch. R10 base (best: 173.9us) + merged
// M-tiles: for NP=200 both 128-row tiles share one K-pass so B fragments are
// read from smem ONCE per kc (L1TEX wavefront diet; L1 is the binder).
// L1 GEMM: A fragments LDG'd directly from global X (barrier-free); B = W^T
// staged once as bank-exact bf16 hi/lo planes. Split-bf16: D = AhBh+AhBl+AlBh.
// agg1 emits bf16 hi/lo planes consumed by layer-2 MMA; agg2 fused w/ pooling.
// Edges cp.async-staged. In-kernel MLP via per-graph atomic ticket.
// rows = repeat(arange(N),16) -> node r owns edges [16r,16r+16); cols in-graph.
// ---------------------------------------------------------------------------

#define BGRAPHS 1024
#define DEG 16

// smem layout (bytes)
#define W1T_B   0        // W1^T hi [32][232] bf16 (464B rows) = 14848
#define W1T_LO  14848    // W1^T lo — dies after L1 GEMM
#define HB_HI_B 0        // hb hi [<=206][36] bf16 (aliases W1T)
#define HB_LO_B 14848
#define WBT_B   29696    // Wb^T hi [32][40] bf16 = 2560
#define WBT_LO  32256
#define SUP_B   34816    // sup [200][34] f32 = 27200
#define COLS_B  62016    // cols i32 [200*16] = 12800
#define VALS_B  74816    // vals f32 [200*16] = 12800
#define RED_B   29696    // pool scratch, aliases WBT (dead by then)
#define SMEM_BYTES 87616

__device__ float g_feat[BGRAPHS * 128];
__device__ int   g_cnt[BGRAPHS];          // zero-init; re-armed after each use

__device__ __forceinline__ void hmma(float* c, uint32_t a0, uint32_t a1,
                                     uint32_t a2, uint32_t a3,
                                     uint32_t b0, uint32_t b1) {
    asm("mma.sync.aligned.m16n8k16.row.col.f32.bf16.bf16.f32 "
        "{%0,%1,%2,%3}, {%4,%5,%6,%7}, {%8,%9}, {%0,%1,%2,%3};"
        : "+f"(c[0]), "+f"(c[1]), "+f"(c[2]), "+f"(c[3])
        : "r"(a0), "r"(a1), "r"(a2), "r"(a3), "r"(b0), "r"(b1));
}
__device__ __forceinline__ void split2(float2 v, uint32_t& h, uint32_t& l) {
    __nv_bfloat162 h2 = __float22bfloat162_rn(v);
    float2 hf = __bfloat1622float2(h2);
    __nv_bfloat162 l2 = __float22bfloat162_rn(make_float2(v.x - hf.x, v.y - hf.y));
    h = *(uint32_t*)&h2;
    l = *(uint32_t*)&l2;
}
__device__ __forceinline__ uint32_t smem_u32(const void* p) {
    return (uint32_t)__cvta_generic_to_shared(p);
}
__device__ __forceinline__ void cp_async16(uint32_t dst, const void* src) {
    asm volatile("cp.async.cg.shared.global [%0], [%1], 16;"
                 :: "r"(dst), "l"(src));
}
__device__ __forceinline__ void cp_commit() {
    asm volatile("cp.async.commit_group;");
}
__device__ __forceinline__ void cp_wait0() {
    asm volatile("cp.async.wait_group 0;");
}

// MLP head for one sample (one warp).
__device__ __forceinline__ void mlp_tail(
    int g, int lane,
    const float* __restrict__ fc1W, const float* __restrict__ fc1b,
    const float* __restrict__ fc2W, const float* __restrict__ fc2b,
    const float* __restrict__ fc3W, const float* __restrict__ fc3b,
    float* __restrict__ out)
{
    const float* f = g_feat + g * 128;
    float fr0 = f[lane];
    float fr1 = f[32 + lane];
    float fr2 = f[64 + lane];
    float fr3 = f[96 + lane];

    float a0 = __ldg(fc1b + lane), a1 = 0.f, a2 = 0.f, a3 = 0.f;
    #pragma unroll
    for (int j = 0; j < 32; j++) {
        float f0 = __shfl_sync(0xffffffffu, fr0, j);
        float f1 = __shfl_sync(0xffffffffu, fr1, j);
        float f2 = __shfl_sync(0xffffffffu, fr2, j);
        float f3 = __shfl_sync(0xffffffffu, fr3, j);
        a0 = fmaf(f0, __ldg(fc1W + j * 32 + lane), a0);
        a1 = fmaf(f1, __ldg(fc1W + (32 + j) * 32 + lane), a1);
        a2 = fmaf(f2, __ldg(fc1W + (64 + j) * 32 + lane), a2);
        a3 = fmaf(f3, __ldg(fc1W + (96 + j) * 32 + lane), a3);
    }
    float h1 = fmaxf((a0 + a1) + (a2 + a3), 0.f);

    const int l16 = lane & 15;
    float b0 = __ldg(fc2b + l16), b1 = 0.f;
    #pragma unroll
    for (int k = 0; k < 32; k += 2) {
        float ha = __shfl_sync(0xffffffffu, h1, k);
        float hb = __shfl_sync(0xffffffffu, h1, k + 1);
        b0 = fmaf(ha, __ldg(fc2W + k * 16 + l16), b0);
        b1 = fmaf(hb, __ldg(fc2W + (k + 1) * 16 + l16), b1);
    }
    float h2 = fmaxf(b0 + b1, 0.f);

    const int l2 = lane & 1;
    float o = __ldg(fc3b + l2);
    #pragma unroll
    for (int k = 0; k < 16; k++) {
        float hk = __shfl_sync(0xffffffffu, h2, k);
        o = fmaf(hk, __ldg(fc3W + k * 2 + l2), o);
    }
    if (lane < 2) out[g * 2 + l2] = o;
}

template<int NP, int KC, int NTILES>
__device__ __forceinline__ void run_branch(
    char* smb, int g,
    const float* __restrict__ X, const int* __restrict__ cols,
    const float* __restrict__ vals,
    const float* __restrict__ Wa, const float* __restrict__ ba,
    const float* __restrict__ Wb, const float* __restrict__ bb, int foff,
    const float* __restrict__ fc1W, const float* __restrict__ fc1b,
    const float* __restrict__ fc2W, const float* __restrict__ fc2b,
    const float* __restrict__ fc3W, const float* __restrict__ fc3b,
    float* __restrict__ out)
{
    float* sup = (float*)(smb + SUP_B);

    const int tid  = threadIdx.x;
    const int lane = tid & 31;
    const int wid  = tid >> 5;
    const int gq   = lane >> 2;
    const int tq   = lane & 3;
    const int gbase = g * NP;
    const float* Xg = X + (size_t)gbase * NP;

    // ---- fire-and-forget: stage this graph's edges into SMEM ----
    {
        const uint32_t sc = smem_u32(smb + COLS_B);
        const uint32_t sv = smem_u32(smb + VALS_B);
        const char* gc = (const char*)(cols + (size_t)gbase * DEG);
        const char* gv = (const char*)(vals + (size_t)gbase * DEG);
        for (int i = tid; i < NP * 4; i += 256) {
            cp_async16(sc + i * 16, gc + i * 16);
            cp_async16(sv + i * 16, gv + i * 16);
        }
        cp_commit();
    }

    // ---- stage W1^T hi/lo planes once ([32][232] bf16 rows, bank-exact) ----
    for (int i = tid; i < 32 * KC * 16; i += 256) {
        int kp = i >> 5, n = i & 31;
        int k = 2 * kp;
        float2 v = make_float2(0.f, 0.f);
        if (k < NP)     v.x = Wa[k * 32 + n];
        if (k + 1 < NP) v.y = Wa[(k + 1) * 32 + n];
        uint32_t h, l;
        split2(v, h, l);
        *(uint32_t*)(smb + W1T_B  + n * 464 + kp * 4) = h;
        *(uint32_t*)(smb + W1T_LO + n * 464 + kp * 4) = l;
    }
    // ---- stage Wb^T hi/lo planes once ([32][40] bf16) ----
    for (int i = tid; i < 32 * 20; i += 256) {
        int kp = i >> 5, n = i & 31;
        int k = 2 * kp;
        float2 v = make_float2(0.f, 0.f);
        if (k < 32) { v.x = Wb[k * 32 + n]; v.y = Wb[(k + 1) * 32 + n]; }
        uint32_t h, l;
        split2(v, h, l);
        *(uint32_t*)(smb + WBT_B  + n * 80 + kp * 4) = h;
        *(uint32_t*)(smb + WBT_LO + n * 80 + kp * 4) = l;
    }
    __syncthreads();

    // =========== Layer 1: sup = X_g @ Wa (merged tiles, barrier-free) ======
    {
        const int rA = wid * 16 + gq;          // tile-0 row of this thread
        const float* pA0 = Xg + (size_t)rA * NP;
        const float* pA1 = pA0 + (size_t)8 * NP;
        const float* pB0 = Xg + (size_t)(rA + 128) * NP;   // tile-1 (NTILES==2)
        const float* pB1 = pB0 + (size_t)8 * NP;

        float acc[NTILES][4][4];
        #pragma unroll
        for (int tt = 0; tt < NTILES; tt++)
            #pragma unroll
            for (int i = 0; i < 4; i++)
                #pragma unroll
                for (int j = 0; j < 4; j++) acc[tt][i][j] = 0.f;

        #pragma unroll
        for (int kc = 0; kc < KC; kc++) {
            // A fragments for both tiles: independent LDGs issued together
            float2 x0[8], x1[NTILES == 2 ? 8 : 1];
            #pragma unroll
            for (int s = 0; s < 2; s++) {
                int ka = kc * 32 + s * 16 + 2 * tq;
                int kb = ka + 8;
                bool oka = (ka < NP), okb = (kb < NP);
                x0[s*4+0] = (rA       < NP && oka) ? *(const float2*)(pA0 + ka) : make_float2(0.f,0.f);
                x0[s*4+1] = (rA + 8   < NP && oka) ? *(const float2*)(pA1 + ka) : make_float2(0.f,0.f);
                x0[s*4+2] = (rA       < NP && okb) ? *(const float2*)(pA0 + kb) : make_float2(0.f,0.f);
                x0[s*4+3] = (rA + 8   < NP && okb) ? *(const float2*)(pA1 + kb) : make_float2(0.f,0.f);
                if (NTILES == 2) {
                    x1[s*4+0] = (rA + 128 < NP && oka) ? *(const float2*)(pB0 + ka) : make_float2(0.f,0.f);
                    x1[s*4+1] = (rA + 136 < NP && oka) ? *(const float2*)(pB1 + ka) : make_float2(0.f,0.f);
                    x1[s*4+2] = (rA + 128 < NP && okb) ? *(const float2*)(pB0 + kb) : make_float2(0.f,0.f);
                    x1[s*4+3] = (rA + 136 < NP && okb) ? *(const float2*)(pB1 + kb) : make_float2(0.f,0.f);
                }
            }
            #pragma unroll
            for (int s = 0; s < 2; s++) {
                uint32_t ah0[4], al0[4], ah1[4], al1[4];
                #pragma unroll
                for (int j = 0; j < 4; j++) {
                    split2(x0[s*4+j], ah0[j], al0[j]);
                    if (NTILES == 2) split2(x1[s*4+j], ah1[j], al1[j]);
                }
                #pragma unroll
                for (int nt = 0; nt < 4; nt++) {
                    const char* p = smb + W1T_B + (nt*8+gq) * 464
                                  + (kc*32 + s*16 + 2*tq) * 2;
                    uint32_t bh0 = *(const uint32_t*)p;
                    uint32_t bh1 = *(const uint32_t*)(p + 16);
                    uint32_t bl0 = *(const uint32_t*)(p + W1T_LO);
                    uint32_t bl1 = *(const uint32_t*)(p + W1T_LO + 16);
                    hmma(acc[0][nt], ah0[0],ah0[1],ah0[2],ah0[3], bh0, bh1);
                    hmma(acc[0][nt], ah0[0],ah0[1],ah0[2],ah0[3], bl0, bl1);
                    hmma(acc[0][nt], al0[0],al0[1],al0[2],al0[3], bh0, bh1);
                    if (NTILES == 2) {
                        hmma(acc[1][nt], ah1[0],ah1[1],ah1[2],ah1[3], bh0, bh1);
                        hmma(acc[1][nt], ah1[0],ah1[1],ah1[2],ah1[3], bl0, bl1);
                        hmma(acc[1][nt], al1[0],al1[1],al1[2],al1[3], bh0, bh1);
                    }
                }
            }
        }
        // epilogue (both tiles)
        #pragma unroll
        for (int tt = 0; tt < NTILES; tt++) {
            int row0 = tt * 128 + rA;
            #pragma unroll
            for (int nt = 0; nt < 4; nt++) {
                if (row0 < NP)
                    *(float2*)(sup + row0 * 34 + nt * 8 + 2 * tq) =
                        make_float2(acc[tt][nt][0], acc[tt][nt][1]);
                if (row0 + 8 < NP)
                    *(float2*)(sup + (row0 + 8) * 34 + nt * 8 + 2 * tq) =
                        make_float2(acc[tt][nt][2], acc[tt][nt][3]);
            }
        }
    }
    cp_wait0();
    __syncthreads();     // sup done; W1T reads done (hb planes may overwrite)

    // ===== agg1: h = relu(A @ sup + b) -> bf16 hi/lo planes =====
    {
        const float bias = __ldg(ba + lane);
        const int*   sc = (const int*)(smb + COLS_B);
        const float* sv = (const float*)(smb + VALS_B);
        const int loff = lane - gbase * 34;
        for (int r = wid; r < NP; r += 8) {
            const int4*   c4 = (const int4*)(sc + r * 16);
            const float4* v4 = (const float4*)(sv + r * 16);
            float a0 = 0.f, a1 = 0.f;
            #pragma unroll
            for (int q = 0; q < 4; q++) {
                int4   ci = c4[q];
                float4 vi = v4[q];
                a0 = fmaf(vi.x, sup[ci.x * 34 + loff], a0);
                a1 = fmaf(vi.y, sup[ci.y * 34 + loff], a1);
                a0 = fmaf(vi.z, sup[ci.z * 34 + loff], a0);
                a1 = fmaf(vi.w, sup[ci.w * 34 + loff], a1);
            }
            float h = fmaxf(a0 + a1 + bias, 0.f);
            __nv_bfloat16 hi = __float2bfloat16(h);
            __nv_bfloat16 lo = __float2bfloat16(h - __bfloat162float(hi));
            *(__nv_bfloat16*)(smb + HB_HI_B + r * 72 + lane * 2) = hi;
            *(__nv_bfloat16*)(smb + HB_LO_B + r * 72 + lane * 2) = lo;
        }
    }
    __syncthreads();

    // ===== Layer 2: sup = hb @ Wb (merged tiles; B read once) =====
    {
        const int rA = wid * 16 + gq;
        float acc[NTILES][4][4];
        #pragma unroll
        for (int tt = 0; tt < NTILES; tt++)
            #pragma unroll
            for (int i = 0; i < 4; i++)
                #pragma unroll
                for (int j = 0; j < 4; j++) acc[tt][i][j] = 0.f;

        const char* A0h = smb + HB_HI_B + rA * 72 + tq * 4;
        const char* A0l = smb + HB_LO_B + rA * 72 + tq * 4;
        #pragma unroll
        for (int s = 0; s < 2; s++) {
            const int so = s * 32;
            uint32_t ah0[4], al0[4], ah1[4], al1[4];
            ah0[0] = *(const uint32_t*)(A0h + so);
            ah0[1] = *(const uint32_t*)(A0h + so + 576);
            ah0[2] = *(const uint32_t*)(A0h + so + 16);
            ah0[3] = *(const uint32_t*)(A0h + so + 576 + 16);
            al0[0] = *(const uint32_t*)(A0l + so);
            al0[1] = *(const uint32_t*)(A0l + so + 576);
            al0[2] = *(const uint32_t*)(A0l + so + 16);
            al0[3] = *(const uint32_t*)(A0l + so + 576 + 16);
            if (NTILES == 2) {
                ah1[0] = *(const uint32_t*)(A0h + so + 9216);        // +128 rows
                ah1[1] = *(const uint32_t*)(A0h + so + 9216 + 576);
                ah1[2] = *(const uint32_t*)(A0h + so + 9216 + 16);
                ah1[3] = *(const uint32_t*)(A0h + so + 9216 + 576 + 16);
                al1[0] = *(const uint32_t*)(A0l + so + 9216);
                al1[1] = *(const uint32_t*)(A0l + so + 9216 + 576);
                al1[2] = *(const uint32_t*)(A0l + so + 9216 + 16);
                al1[3] = *(const uint32_t*)(A0l + so + 9216 + 576 + 16);
            }
            #pragma unroll
            for (int nt = 0; nt < 4; nt++) {
                const char* Bn = smb + WBT_B  + (nt*8+gq) * 80 + tq * 4 + so;
                const char* Bl = smb + WBT_LO + (nt*8+gq) * 80 + tq * 4 + so;
                uint32_t bh0 = *(const uint32_t*)(Bn);
                uint32_t bh1 = *(const uint32_t*)(Bn + 16);
                uint32_t bl0 = *(const uint32_t*)(Bl);
                uint32_t bl1 = *(const uint32_t*)(Bl + 16);
                hmma(acc[0][nt], ah0[0],ah0[1],ah0[2],ah0[3], bh0, bh1);
                hmma(acc[0][nt], ah0[0],ah0[1],ah0[2],ah0[3], bl0, bl1);
                hmma(acc[0][nt], al0[0],al0[1],al0[2],al0[3], bh0, bh1);
                if (NTILES == 2) {
                    hmma(acc[1][nt], ah1[0],ah1[1],ah1[2],ah1[3], bh0, bh1);
                    hmma(acc[1][nt], ah1[0],ah1[1],ah1[2],ah1[3], bl0, bl1);
                    hmma(acc[1][nt], al1[0],al1[1],al1[2],al1[3], bh0, bh1);
                }
            }
        }
        #pragma unroll
        for (int tt = 0; tt < NTILES; tt++) {
            int row0 = tt * 128 + rA;
            #pragma unroll
            for (int nt = 0; nt < 4; nt++) {
                if (row0 < NP)
                    *(float2*)(sup + row0 * 34 + nt * 8 + 2 * tq) =
                        make_float2(acc[tt][nt][0], acc[tt][nt][1]);
                if (row0 + 8 < NP)
                    *(float2*)(sup + (row0 + 8) * 34 + nt * 8 + 2 * tq) =
                        make_float2(acc[tt][nt][2], acc[tt][nt][3]);
            }
        }
    }
    __syncthreads();

    // ===== agg2 + pooling fused =====
    {
        const float bias = __ldg(bb + lane);
        const int*   sc = (const int*)(smb + COLS_B);
        const float* sv = (const float*)(smb + VALS_B);
        const int loff = lane - gbase * 34;
        float s = 0.f, m = -3.4e38f;
        for (int r = wid; r < NP; r += 8) {
            const int4*   c4 = (const int4*)(sc + r * 16);
            const float4* v4 = (const float4*)(sv + r * 16);
            float a0 = 0.f, a1 = 0.f;
            #pragma unroll
            for (int q = 0; q < 4; q++) {
                int4   ci = c4[q];
                float4 vi = v4[q];
                a0 = fmaf(vi.x, sup[ci.x * 34 + loff], a0);
                a1 = fmaf(vi.y, sup[ci.y * 34 + loff], a1);
                a0 = fmaf(vi.z, sup[ci.z * 34 + loff], a0);
                a1 = fmaf(vi.w, sup[ci.w * 34 + loff], a1);
            }
            float h = fmaxf(a0 + a1 + bias, 0.f);
            s += h;
            m = fmaxf(m, h);
        }
        float* redS = (float*)(smb + RED_B);   // aliases WBT (dead now)
        float* redM = redS + 256;
        redS[wid * 32 + lane] = s;
        redM[wid * 32 + lane] = m;
        __syncthreads();
        if (wid == 0) {
            float ss = 0.f, mm = -3.4e38f;
            #pragma unroll
            for (int i = 0; i < 8; i++) {
                ss += redS[i * 32 + lane];
                mm = fmaxf(mm, redM[i * 32 + lane]);
            }
            g_feat[g * 128 + foff + lane]      = ss / (float)NP;
            g_feat[g * 128 + foff + 32 + lane] = mm;

            // ---- MLP ticket: second CTA to finish this graph computes it ----
            __threadfence();
            __syncwarp();
            int old = 0;
            if (lane == 0) old = atomicAdd(&g_cnt[g], 1);
            old = __shfl_sync(0xffffffffu, old, 0);
            if (old == 1) {
                __threadfence();
                mlp_tail(g, lane, fc1W, fc1b, fc2W, fc2b, fc3W, fc3b, out);
                if (lane == 0) g_cnt[g] = 0;   // re-arm for graph replay
            }
        }
    }
}

__global__ void __launch_bounds__(256, 2)
branch_kernel(const float* __restrict__ x1, const int* __restrict__ cols1,
              const float* __restrict__ vals1,
              const float* __restrict__ W1a, const float* __restrict__ b1a,
              const float* __restrict__ W1b, const float* __restrict__ b1b,
              const float* __restrict__ x2, const int* __restrict__ cols2,
              const float* __restrict__ vals2,
              const float* __restrict__ W2a, const float* __restrict__ b2a,
              const float* __restrict__ W2b, const float* __restrict__ b2b,
              const float* __restrict__ fc1W, const float* __restrict__ fc1b,
              const float* __restrict__ fc2W, const float* __restrict__ fc2b,
              const float* __restrict__ fc3W, const float* __restrict__ fc3b,
              float* __restrict__ out)
{
    extern __shared__ char smb[];
    const int bid = blockIdx.x;
    if (bid < BGRAPHS) {
        run_branch<200, 7, 2>(smb, bid, x2, cols2, vals2, W2a, b2a, W2b, b2b, 64,
                              fc1W, fc1b, fc2W, fc2b, fc3W, fc3b, out);
    } else {
        run_branch<116, 4, 1>(smb, bid - BGRAPHS, x1, cols1, vals1,
                              W1a, b1a, W1b, b1b, 0,
                              fc1W, fc1b, fc2W, fc2b, fc3W, fc3b, out);
    }
}

extern "C" void kernel_launch(void* const* d_in, const int* in_sizes, int n_in,
                              void* d_out, int out_size)
{
    (void)in_sizes; (void)n_in; (void)out_size;
    const int*   cols1 = (const int*)  d_in[1];
    const float* vals1 = (const float*)d_in[2];
    const float* x1    = (const float*)d_in[3];
    const int*   cols2 = (const int*)  d_in[5];
    const float* vals2 = (const float*)d_in[6];
    const float* x2    = (const float*)d_in[7];
    const float* W1a  = (const float*)d_in[8];
    const float* b1a  = (const float*)d_in[9];
    const float* W1b  = (const float*)d_in[10];
    const float* b1b  = (const float*)d_in[11];
    const float* W2a  = (const float*)d_in[12];
    const float* b2a  = (const float*)d_in[13];
    const float* W2b  = (const float*)d_in[14];
    const float* b2b  = (const float*)d_in[15];
    const float* fc1W = (const float*)d_in[16];
    const float* fc1b = (const float*)d_in[17];
    const float* fc2W = (const float*)d_in[18];
    const float* fc2b = (const float*)d_in[19];
    const float* fc3W = (const float*)d_in[20];
    const float* fc3b = (const float*)d_in[21];
    float* out = (float*)d_out;

    cudaFuncSetAttribute(branch_kernel,
                         cudaFuncAttributeMaxDynamicSharedMemorySize, SMEM_BYTES);

    branch_kernel<<<2 * BGRAPHS, 256, SMEM_BYTES>>>(
        x1, cols1, vals1, W1a, b1a, W1b, b1b,
        x2, cols2, vals2, W2a, b2a, W2b, b2b,
        fc1W, fc1b, fc2W, fc2b, fc3W, fc3b, out);
}

// round 13
// speedup vs baseline: 1.0907x; 1.0347x over previous
#include <cuda_runtime.h>
#include <cuda_bf16.h>
#include <cstdint>

// ---------------------------------------------------------------------------
// Dual-branch GCN + MLP, single launch. R12 base (best: 170.0us) + agg
// broadcast diet: edge cols stored as u8 LOCAL indices (1 LDS.128 broadcast
// per row instead of 4), vals kept f32 in smem (cp.async). L1TEX wavefronts
// are the binder; this removes ~1200 wf per big CTA.
// GEMMs: warp mma.sync m16n8k16 bf16 split-bf16 (D = AhBh+AhBl+AlBh), merged
// M-tiles (B fragments read once per kc). A LDG'd direct from global X.
// agg1 emits bf16 hi/lo planes consumed by layer-2 MMA; agg2 fused w/ pooling.
// In-kernel MLP via per-graph atomic ticket.
// rows = repeat(arange(N),16) -> node r owns edges [16r,16r+16); cols in-graph.
// ---------------------------------------------------------------------------

#define BGRAPHS 1024
#define DEG 16

// smem layout (bytes)
#define W1T_B   0        // W1^T hi [32][232] bf16 (464B rows) = 14848
#define W1T_LO  14848    // W1^T lo — dies after L1 GEMM
#define HB_HI_B 0        // hb hi [<=206][36] bf16 (aliases W1T)
#define HB_LO_B 14848
#define WBT_B   29696    // Wb^T hi [32][40] bf16 = 2560
#define WBT_LO  32256
#define SUP_B   34816    // sup [200][34] f32 = 27200
#define COLS_B  62016    // u8 local cols [200*16] = 3200
#define VALS_B  65216    // vals f32 [200*16] = 12800
#define RED_B   29696    // pool scratch, aliases WBT (dead by then)
#define SMEM_BYTES 78016

__device__ float g_feat[BGRAPHS * 128];
__device__ int   g_cnt[BGRAPHS];          // zero-init; re-armed after each use

__device__ __forceinline__ void hmma(float* c, uint32_t a0, uint32_t a1,
                                     uint32_t a2, uint32_t a3,
                                     uint32_t b0, uint32_t b1) {
    asm("mma.sync.aligned.m16n8k16.row.col.f32.bf16.bf16.f32 "
        "{%0,%1,%2,%3}, {%4,%5,%6,%7}, {%8,%9}, {%0,%1,%2,%3};"
        : "+f"(c[0]), "+f"(c[1]), "+f"(c[2]), "+f"(c[3])
        : "r"(a0), "r"(a1), "r"(a2), "r"(a3), "r"(b0), "r"(b1));
}
__device__ __forceinline__ void split2(float2 v, uint32_t& h, uint32_t& l) {
    __nv_bfloat162 h2 = __float22bfloat162_rn(v);
    float2 hf = __bfloat1622float2(h2);
    __nv_bfloat162 l2 = __float22bfloat162_rn(make_float2(v.x - hf.x, v.y - hf.y));
    h = *(uint32_t*)&h2;
    l = *(uint32_t*)&l2;
}
__device__ __forceinline__ uint32_t smem_u32(const void* p) {
    return (uint32_t)__cvta_generic_to_shared(p);
}
__device__ __forceinline__ void cp_async16(uint32_t dst, const void* src) {
    asm volatile("cp.async.cg.shared.global [%0], [%1], 16;"
                 :: "r"(dst), "l"(src));
}
__device__ __forceinline__ void cp_commit() {
    asm volatile("cp.async.commit_group;");
}
__device__ __forceinline__ void cp_wait0() {
    asm volatile("cp.async.wait_group 0;");
}

// MLP head for one sample (one warp).
__device__ __forceinline__ void mlp_tail(
    int g, int lane,
    const float* __restrict__ fc1W, const float* __restrict__ fc1b,
    const float* __restrict__ fc2W, const float* __restrict__ fc2b,
    const float* __restrict__ fc3W, const float* __restrict__ fc3b,
    float* __restrict__ out)
{
    const float* f = g_feat + g * 128;
    float fr0 = f[lane];
    float fr1 = f[32 + lane];
    float fr2 = f[64 + lane];
    float fr3 = f[96 + lane];

    float a0 = __ldg(fc1b + lane), a1 = 0.f, a2 = 0.f, a3 = 0.f;
    #pragma unroll
    for (int j = 0; j < 32; j++) {
        float f0 = __shfl_sync(0xffffffffu, fr0, j);
        float f1 = __shfl_sync(0xffffffffu, fr1, j);
        float f2 = __shfl_sync(0xffffffffu, fr2, j);
        float f3 = __shfl_sync(0xffffffffu, fr3, j);
        a0 = fmaf(f0, __ldg(fc1W + j * 32 + lane), a0);
        a1 = fmaf(f1, __ldg(fc1W + (32 + j) * 32 + lane), a1);
        a2 = fmaf(f2, __ldg(fc1W + (64 + j) * 32 + lane), a2);
        a3 = fmaf(f3, __ldg(fc1W + (96 + j) * 32 + lane), a3);
    }
    float h1 = fmaxf((a0 + a1) + (a2 + a3), 0.f);

    const int l16 = lane & 15;
    float b0 = __ldg(fc2b + l16), b1 = 0.f;
    #pragma unroll
    for (int k = 0; k < 32; k += 2) {
        float ha = __shfl_sync(0xffffffffu, h1, k);
        float hb = __shfl_sync(0xffffffffu, h1, k + 1);
        b0 = fmaf(ha, __ldg(fc2W + k * 16 + l16), b0);
        b1 = fmaf(hb, __ldg(fc2W + (k + 1) * 16 + l16), b1);
    }
    float h2 = fmaxf(b0 + b1, 0.f);

    const int l2 = lane & 1;
    float o = __ldg(fc3b + l2);
    #pragma unroll
    for (int k = 0; k < 16; k++) {
        float hk = __shfl_sync(0xffffffffu, h2, k);
        o = fmaf(hk, __ldg(fc3W + k * 2 + l2), o);
    }
    if (lane < 2) out[g * 2 + l2] = o;
}

template<int NP, int KC, int NTILES>
__device__ __forceinline__ void run_branch(
    char* smb, int g,
    const float* __restrict__ X, const int* __restrict__ cols,
    const float* __restrict__ vals,
    const float* __restrict__ Wa, const float* __restrict__ ba,
    const float* __restrict__ Wb, const float* __restrict__ bb, int foff,
    const float* __restrict__ fc1W, const float* __restrict__ fc1b,
    const float* __restrict__ fc2W, const float* __restrict__ fc2b,
    const float* __restrict__ fc3W, const float* __restrict__ fc3b,
    float* __restrict__ out)
{
    float* sup = (float*)(smb + SUP_B);

    const int tid  = threadIdx.x;
    const int lane = tid & 31;
    const int wid  = tid >> 5;
    const int gq   = lane >> 2;
    const int tq   = lane & 3;
    const int gbase = g * NP;
    const float* Xg = X + (size_t)gbase * NP;

    // ---- stage edges: vals via cp.async (f32), cols packed to u8 local ----
    {
        const uint32_t sv = smem_u32(smb + VALS_B);
        const char* gv = (const char*)(vals + (size_t)gbase * DEG);
        for (int i = tid; i < NP * 4; i += 256)
            cp_async16(sv + i * 16, gv + i * 16);
        cp_commit();

        const int4* gc = (const int4*)(cols + (size_t)gbase * DEG);
        for (int i = tid; i < NP * 4; i += 256) {
            int4 c = __ldg(gc + i);
            uint32_t p = (uint32_t)(c.x - gbase)
                       | ((uint32_t)(c.y - gbase) << 8)
                       | ((uint32_t)(c.z - gbase) << 16)
                       | ((uint32_t)(c.w - gbase) << 24);
            *(uint32_t*)(smb + COLS_B + i * 4) = p;
        }
    }

    // ---- stage W1^T hi/lo planes once ([32][232] bf16 rows, bank-exact) ----
    for (int i = tid; i < 32 * KC * 16; i += 256) {
        int kp = i >> 5, n = i & 31;
        int k = 2 * kp;
        float2 v = make_float2(0.f, 0.f);
        if (k < NP)     v.x = Wa[k * 32 + n];
        if (k + 1 < NP) v.y = Wa[(k + 1) * 32 + n];
        uint32_t h, l;
        split2(v, h, l);
        *(uint32_t*)(smb + W1T_B  + n * 464 + kp * 4) = h;
        *(uint32_t*)(smb + W1T_LO + n * 464 + kp * 4) = l;
    }
    // ---- stage Wb^T hi/lo planes once ([32][40] bf16) ----
    for (int i = tid; i < 32 * 20; i += 256) {
        int kp = i >> 5, n = i & 31;
        int k = 2 * kp;
        float2 v = make_float2(0.f, 0.f);
        if (k < 32) { v.x = Wb[k * 32 + n]; v.y = Wb[(k + 1) * 32 + n]; }
        uint32_t h, l;
        split2(v, h, l);
        *(uint32_t*)(smb + WBT_B  + n * 80 + kp * 4) = h;
        *(uint32_t*)(smb + WBT_LO + n * 80 + kp * 4) = l;
    }
    __syncthreads();

    // =========== Layer 1: sup = X_g @ Wa (merged tiles, barrier-free) ======
    {
        const int rA = wid * 16 + gq;          // tile-0 row of this thread
        const float* pA0 = Xg + (size_t)rA * NP;
        const float* pA1 = pA0 + (size_t)8 * NP;
        const float* pB0 = Xg + (size_t)(rA + 128) * NP;   // tile-1 (NTILES==2)
        const float* pB1 = pB0 + (size_t)8 * NP;

        float acc[NTILES][4][4];
        #pragma unroll
        for (int tt = 0; tt < NTILES; tt++)
            #pragma unroll
            for (int i = 0; i < 4; i++)
                #pragma unroll
                for (int j = 0; j < 4; j++) acc[tt][i][j] = 0.f;

        #pragma unroll
        for (int kc = 0; kc < KC; kc++) {
            float2 x0[8], x1[NTILES == 2 ? 8 : 1];
            #pragma unroll
            for (int s = 0; s < 2; s++) {
                int ka = kc * 32 + s * 16 + 2 * tq;
                int kb = ka + 8;
                bool oka = (ka < NP), okb = (kb < NP);
                x0[s*4+0] = (rA       < NP && oka) ? *(const float2*)(pA0 + ka) : make_float2(0.f,0.f);
                x0[s*4+1] = (rA + 8   < NP && oka) ? *(const float2*)(pA1 + ka) : make_float2(0.f,0.f);
                x0[s*4+2] = (rA       < NP && okb) ? *(const float2*)(pA0 + kb) : make_float2(0.f,0.f);
                x0[s*4+3] = (rA + 8   < NP && okb) ? *(const float2*)(pA1 + kb) : make_float2(0.f,0.f);
                if (NTILES == 2) {
                    x1[s*4+0] = (rA + 128 < NP && oka) ? *(const float2*)(pB0 + ka) : make_float2(0.f,0.f);
                    x1[s*4+1] = (rA + 136 < NP && oka) ? *(const float2*)(pB1 + ka) : make_float2(0.f,0.f);
                    x1[s*4+2] = (rA + 128 < NP && okb) ? *(const float2*)(pB0 + kb) : make_float2(0.f,0.f);
                    x1[s*4+3] = (rA + 136 < NP && okb) ? *(const float2*)(pB1 + kb) : make_float2(0.f,0.f);
                }
            }
            #pragma unroll
            for (int s = 0; s < 2; s++) {
                uint32_t ah0[4], al0[4], ah1[4], al1[4];
                #pragma unroll
                for (int j = 0; j < 4; j++) {
                    split2(x0[s*4+j], ah0[j], al0[j]);
                    if (NTILES == 2) split2(x1[s*4+j], ah1[j], al1[j]);
                }
                #pragma unroll
                for (int nt = 0; nt < 4; nt++) {
                    const char* p = smb + W1T_B + (nt*8+gq) * 464
                                  + (kc*32 + s*16 + 2*tq) * 2;
                    uint32_t bh0 = *(const uint32_t*)p;
                    uint32_t bh1 = *(const uint32_t*)(p + 16);
                    uint32_t bl0 = *(const uint32_t*)(p + W1T_LO);
                    uint32_t bl1 = *(const uint32_t*)(p + W1T_LO + 16);
                    hmma(acc[0][nt], ah0[0],ah0[1],ah0[2],ah0[3], bh0, bh1);
                    hmma(acc[0][nt], ah0[0],ah0[1],ah0[2],ah0[3], bl0, bl1);
                    hmma(acc[0][nt], al0[0],al0[1],al0[2],al0[3], bh0, bh1);
                    if (NTILES == 2) {
                        hmma(acc[1][nt], ah1[0],ah1[1],ah1[2],ah1[3], bh0, bh1);
                        hmma(acc[1][nt], ah1[0],ah1[1],ah1[2],ah1[3], bl0, bl1);
                        hmma(acc[1][nt], al1[0],al1[1],al1[2],al1[3], bh0, bh1);
                    }
                }
            }
        }
        #pragma unroll
        for (int tt = 0; tt < NTILES; tt++) {
            int row0 = tt * 128 + rA;
            #pragma unroll
            for (int nt = 0; nt < 4; nt++) {
                if (row0 < NP)
                    *(float2*)(sup + row0 * 34 + nt * 8 + 2 * tq) =
                        make_float2(acc[tt][nt][0], acc[tt][nt][1]);
                if (row0 + 8 < NP)
                    *(float2*)(sup + (row0 + 8) * 34 + nt * 8 + 2 * tq) =
                        make_float2(acc[tt][nt][2], acc[tt][nt][3]);
            }
        }
    }
    cp_wait0();
    __syncthreads();     // sup done; W1T reads done (hb planes may overwrite)

    // ===== agg1: h = relu(A @ sup + b) -> bf16 hi/lo planes =====
    {
        const float bias = __ldg(ba + lane);
        const float* supl = sup + lane;
        for (int r = wid; r < NP; r += 8) {
            uint4 cw = *(const uint4*)(smb + COLS_B + r * 16);
            const float4* v4 = (const float4*)(smb + VALS_B + r * 64);
            float4 v0 = v4[0], v1 = v4[1], v2 = v4[2], v3 = v4[3];
            float a0 = 0.f, a1 = 0.f;
            a0 = fmaf(v0.x, supl[( cw.x        & 255) * 34], a0);
            a1 = fmaf(v0.y, supl[((cw.x >>  8) & 255) * 34], a1);
            a0 = fmaf(v0.z, supl[((cw.x >> 16) & 255) * 34], a0);
            a1 = fmaf(v0.w, supl[( cw.x >> 24       ) * 34], a1);
            a0 = fmaf(v1.x, supl[( cw.y        & 255) * 34], a0);
            a1 = fmaf(v1.y, supl[((cw.y >>  8) & 255) * 34], a1);
            a0 = fmaf(v1.z, supl[((cw.y >> 16) & 255) * 34], a0);
            a1 = fmaf(v1.w, supl[( cw.y >> 24       ) * 34], a1);
            a0 = fmaf(v2.x, supl[( cw.z        & 255) * 34], a0);
            a1 = fmaf(v2.y, supl[((cw.z >>  8) & 255) * 34], a1);
            a0 = fmaf(v2.z, supl[((cw.z >> 16) & 255) * 34], a0);
            a1 = fmaf(v2.w, supl[( cw.z >> 24       ) * 34], a1);
            a0 = fmaf(v3.x, supl[( cw.w        & 255) * 34], a0);
            a1 = fmaf(v3.y, supl[((cw.w >>  8) & 255) * 34], a1);
            a0 = fmaf(v3.z, supl[((cw.w >> 16) & 255) * 34], a0);
            a1 = fmaf(v3.w, supl[( cw.w >> 24       ) * 34], a1);
            float h = fmaxf(a0 + a1 + bias, 0.f);
            __nv_bfloat16 hi = __float2bfloat16(h);
            __nv_bfloat16 lo = __float2bfloat16(h - __bfloat162float(hi));
            *(__nv_bfloat16*)(smb + HB_HI_B + r * 72 + lane * 2) = hi;
            *(__nv_bfloat16*)(smb + HB_LO_B + r * 72 + lane * 2) = lo;
        }
    }
    __syncthreads();

    // ===== Layer 2: sup = hb @ Wb (merged tiles; B read once) =====
    {
        const int rA = wid * 16 + gq;
        float acc[NTILES][4][4];
        #pragma unroll
        for (int tt = 0; tt < NTILES; tt++)
            #pragma unroll
            for (int i = 0; i < 4; i++)
                #pragma unroll
                for (int j = 0; j < 4; j++) acc[tt][i][j] = 0.f;

        const char* A0h = smb + HB_HI_B + rA * 72 + tq * 4;
        const char* A0l = smb + HB_LO_B + rA * 72 + tq * 4;
        #pragma unroll
        for (int s = 0; s < 2; s++) {
            const int so = s * 32;
            uint32_t ah0[4], al0[4], ah1[4], al1[4];
            ah0[0] = *(const uint32_t*)(A0h + so);
            ah0[1] = *(const uint32_t*)(A0h + so + 576);
            ah0[2] = *(const uint32_t*)(A0h + so + 16);
            ah0[3] = *(const uint32_t*)(A0h + so + 576 + 16);
            al0[0] = *(const uint32_t*)(A0l + so);
            al0[1] = *(const uint32_t*)(A0l + so + 576);
            al0[2] = *(const uint32_t*)(A0l + so + 16);
            al0[3] = *(const uint32_t*)(A0l + so + 576 + 16);
            if (NTILES == 2) {
                ah1[0] = *(const uint32_t*)(A0h + so + 9216);        // +128 rows
                ah1[1] = *(const uint32_t*)(A0h + so + 9216 + 576);
                ah1[2] = *(const uint32_t*)(A0h + so + 9216 + 16);
                ah1[3] = *(const uint32_t*)(A0h + so + 9216 + 576 + 16);
                al1[0] = *(const uint32_t*)(A0l + so + 9216);
                al1[1] = *(const uint32_t*)(A0l + so + 9216 + 576);
                al1[2] = *(const uint32_t*)(A0l + so + 9216 + 16);
                al1[3] = *(const uint32_t*)(A0l + so + 9216 + 576 + 16);
            }
            #pragma unroll
            for (int nt = 0; nt < 4; nt++) {
                const char* Bn = smb + WBT_B  + (nt*8+gq) * 80 + tq * 4 + so;
                const char* Bl = smb + WBT_LO + (nt*8+gq) * 80 + tq * 4 + so;
                uint32_t bh0 = *(const uint32_t*)(Bn);
                uint32_t bh1 = *(const uint32_t*)(Bn + 16);
                uint32_t bl0 = *(const uint32_t*)(Bl);
                uint32_t bl1 = *(const uint32_t*)(Bl + 16);
                hmma(acc[0][nt], ah0[0],ah0[1],ah0[2],ah0[3], bh0, bh1);
                hmma(acc[0][nt], ah0[0],ah0[1],ah0[2],ah0[3], bl0, bl1);
                hmma(acc[0][nt], al0[0],al0[1],al0[2],al0[3], bh0, bh1);
                if (NTILES == 2) {
                    hmma(acc[1][nt], ah1[0],ah1[1],ah1[2],ah1[3], bh0, bh1);
                    hmma(acc[1][nt], ah1[0],ah1[1],ah1[2],ah1[3], bl0, bl1);
                    hmma(acc[1][nt], al1[0],al1[1],al1[2],al1[3], bh0, bh1);
                }
            }
        }
        #pragma unroll
        for (int tt = 0; tt < NTILES; tt++) {
            int row0 = tt * 128 + rA;
            #pragma unroll
            for (int nt = 0; nt < 4; nt++) {
                if (row0 < NP)
                    *(float2*)(sup + row0 * 34 + nt * 8 + 2 * tq) =
                        make_float2(acc[tt][nt][0], acc[tt][nt][1]);
                if (row0 + 8 < NP)
                    *(float2*)(sup + (row0 + 8) * 34 + nt * 8 + 2 * tq) =
                        make_float2(acc[tt][nt][2], acc[tt][nt][3]);
            }
        }
    }
    __syncthreads();

    // ===== agg2 + pooling fused =====
    {
        const float bias = __ldg(bb + lane);
        const float* supl = sup + lane;
        float s = 0.f, m = -3.4e38f;
        for (int r = wid; r < NP; r += 8) {
            uint4 cw = *(const uint4*)(smb + COLS_B + r * 16);
            const float4* v4 = (const float4*)(smb + VALS_B + r * 64);
            float4 v0 = v4[0], v1 = v4[1], v2 = v4[2], v3 = v4[3];
            float a0 = 0.f, a1 = 0.f;
            a0 = fmaf(v0.x, supl[( cw.x        & 255) * 34], a0);
            a1 = fmaf(v0.y, supl[((cw.x >>  8) & 255) * 34], a1);
            a0 = fmaf(v0.z, supl[((cw.x >> 16) & 255) * 34], a0);
            a1 = fmaf(v0.w, supl[( cw.x >> 24       ) * 34], a1);
            a0 = fmaf(v1.x, supl[( cw.y        & 255) * 34], a0);
            a1 = fmaf(v1.y, supl[((cw.y >>  8) & 255) * 34], a1);
            a0 = fmaf(v1.z, supl[((cw.y >> 16) & 255) * 34], a0);
            a1 = fmaf(v1.w, supl[( cw.y >> 24       ) * 34], a1);
            a0 = fmaf(v2.x, supl[( cw.z        & 255) * 34], a0);
            a1 = fmaf(v2.y, supl[((cw.z >>  8) & 255) * 34], a1);
            a0 = fmaf(v2.z, supl[((cw.z >> 16) & 255) * 34], a0);
            a1 = fmaf(v2.w, supl[( cw.z >> 24       ) * 34], a1);
            a0 = fmaf(v3.x, supl[( cw.w        & 255) * 34], a0);
            a1 = fmaf(v3.y, supl[((cw.w >>  8) & 255) * 34], a1);
            a0 = fmaf(v3.z, supl[((cw.w >> 16) & 255) * 34], a0);
            a1 = fmaf(v3.w, supl[( cw.w >> 24       ) * 34], a1);
            float h = fmaxf(a0 + a1 + bias, 0.f);
            s += h;
            m = fmaxf(m, h);
        }
        float* redS = (float*)(smb + RED_B);   // aliases WBT (dead now)
        float* redM = redS + 256;
        redS[wid * 32 + lane] = s;
        redM[wid * 32 + lane] = m;
        __syncthreads();
        if (wid == 0) {
            float ss = 0.f, mm = -3.4e38f;
            #pragma unroll
            for (int i = 0; i < 8; i++) {
                ss += redS[i * 32 + lane];
                mm = fmaxf(mm, redM[i * 32 + lane]);
            }
            g_feat[g * 128 + foff + lane]      = ss / (float)NP;
            g_feat[g * 128 + foff + 32 + lane] = mm;

            // ---- MLP ticket: second CTA to finish this graph computes it ----
            __threadfence();
            __syncwarp();
            int old = 0;
            if (lane == 0) old = atomicAdd(&g_cnt[g], 1);
            old = __shfl_sync(0xffffffffu, old, 0);
            if (old == 1) {
                __threadfence();
                mlp_tail(g, lane, fc1W, fc1b, fc2W, fc2b, fc3W, fc3b, out);
                if (lane == 0) g_cnt[g] = 0;   // re-arm for graph replay
            }
        }
    }
}

__global__ void __launch_bounds__(256, 2)
branch_kernel(const float* __restrict__ x1, const int* __restrict__ cols1,
              const float* __restrict__ vals1,
              const float* __restrict__ W1a, const float* __restrict__ b1a,
              const float* __restrict__ W1b, const float* __restrict__ b1b,
              const float* __restrict__ x2, const int* __restrict__ cols2,
              const float* __restrict__ vals2,
              const float* __restrict__ W2a, const float* __restrict__ b2a,
              const float* __restrict__ W2b, const float* __restrict__ b2b,
              const float* __restrict__ fc1W, const float* __restrict__ fc1b,
              const float* __restrict__ fc2W, const float* __restrict__ fc2b,
              const float* __restrict__ fc3W, const float* __restrict__ fc3b,
              float* __restrict__ out)
{
    extern __shared__ char smb[];
    const int bid = blockIdx.x;
    if (bid < BGRAPHS) {
        run_branch<200, 7, 2>(smb, bid, x2, cols2, vals2, W2a, b2a, W2b, b2b, 64,
                              fc1W, fc1b, fc2W, fc2b, fc3W, fc3b, out);
    } else {
        run_branch<116, 4, 1>(smb, bid - BGRAPHS, x1, cols1, vals1,
                              W1a, b1a, W1b, b1b, 0,
                              fc1W, fc1b, fc2W, fc2b, fc3W, fc3b, out);
    }
}

extern "C" void kernel_launch(void* const* d_in, const int* in_sizes, int n_in,
                              void* d_out, int out_size)
{
    (void)in_sizes; (void)n_in; (void)out_size;
    const int*   cols1 = (const int*)  d_in[1];
    const float* vals1 = (const float*)d_in[2];
    const float* x1    = (const float*)d_in[3];
    const int*   cols2 = (const int*)  d_in[5];
    const float* vals2 = (const float*)d_in[6];
    const float* x2    = (const float*)d_in[7];
    const float* W1a  = (const float*)d_in[8];
    const float* b1a  = (const float*)d_in[9];
    const float* W1b  = (const float*)d_in[10];
    const float* b1b  = (const float*)d_in[11];
    const float* W2a  = (const float*)d_in[12];
    const float* b2a  = (const float*)d_in[13];
    const float* W2b  = (const float*)d_in[14];
    const float* b2b  = (const float*)d_in[15];
    const float* fc1W = (const float*)d_in[16];
    const float* fc1b = (const float*)d_in[17];
    const float* fc2W = (const float*)d_in[18];
    const float* fc2b = (const float*)d_in[19];
    const float* fc3W = (const float*)d_in[20];
    const float* fc3b = (const float*)d_in[21];
    float* out = (float*)d_out;

    cudaFuncSetAttribute(branch_kernel,
                         cudaFuncAttributeMaxDynamicSharedMemorySize, SMEM_BYTES);

    branch_kernel<<<2 * BGRAPHS, 256, SMEM_BYTES>>>(
        x1, cols1, vals1, W1a, b1a, W1b, b1b,
        x2, cols2, vals2, W2a, b2a, W2b, b2b,
        fc1W, fc1b, fc2W, fc2b, fc3W, fc3b, out);
}